// round 15
// baseline (speedup 1.0000x reference)
#include <cuda_runtime.h>
#include <stdint.h>

#define NBINS     100
#define THREADS_H 1024        // 2 blocks/SM -> 64 warps = full occ
#define GRID_H    296         // 148 SMs * 2 blocks, all co-resident (safe grid sync)
#define TBL       (NBINS * NBINS)   // 10000-entry 2D pair table

__device__ float                 g_bmin[GRID_H];
__device__ float                 g_bmax[GRID_H];
__device__ unsigned int          g_hist[NBINS];  // zero-init; finalize restores zero
__device__ unsigned int          g_done;         // finalize ticket; restored to 0
__device__ volatile unsigned int g_sync1;        // phase-1 barrier; restored to 0

// hmin is the true data min, so (x - hmin) >= 0 exactly; only the upper clamp
// is needed. Keep FADD+FMUL (not fused) to match reference rounding exactly.
__device__ __forceinline__ int bin_of(float x, float hmin, float scale) {
    float d = (x - hmin) * scale;
    int b = __float2int_rd(d);
    return min(b, NBINS - 1);
}

__device__ __forceinline__ void pair_add(unsigned int* t2, const float4& v,
                                         float hmin, float scale) {
    atomicAdd(&t2[bin_of(v.x, hmin, scale) * NBINS + bin_of(v.y, hmin, scale)], 1u);
    atomicAdd(&t2[bin_of(v.z, hmin, scale) * NBINS + bin_of(v.w, hmin, scale)], 1u);
}

__device__ __forceinline__ void mm4(const float4& v, float& mn, float& mx) {
    mn = fminf(mn, fminf(fminf(v.x, v.y), fminf(v.z, v.w)));
    mx = fmaxf(mx, fmaxf(fmaxf(v.x, v.y), fmaxf(v.z, v.w)));
}

// Fused persistent kernel:
//   phase 1: forward min/max sweep, 8 LDG.128 in flight, split accumulators
//   grid barrier (all 296 blocks co-resident; nanosleep spin)
//   phase 2: reverse pair-binning hist, 8 independent float4 loads in flight
//   L2 carryover: fwd->rev within the run, rev->fwd across graph replays.
__global__ void __launch_bounds__(THREADS_H, 2)
fused_kernel(const float* __restrict__ x, int n, float* __restrict__ out) {
    __shared__ unsigned int t2[TBL];        // 40 KB pair table
    __shared__ float s_hmin, s_hmax;

    const int tid = threadIdx.x;
    int n4 = n >> 2;
    const float4* __restrict__ x4 = (const float4*)x;
    const int stride = GRID_H * THREADS_H;

    // ================= phase 1: min/max (forward, 8x unroll) =================
    {
        float mn0 =  3.402823466e+38f, mn1 =  3.402823466e+38f;
        float mx0 = -3.402823466e+38f, mx1 = -3.402823466e+38f;

        int i = blockIdx.x * THREADS_H + tid;
        for (; i + 7 * stride < n4; i += 8 * stride) {
            float4 v0 = x4[i];
            float4 v1 = x4[i + stride];
            float4 v2 = x4[i + 2 * stride];
            float4 v3 = x4[i + 3 * stride];
            float4 v4 = x4[i + 4 * stride];
            float4 v5 = x4[i + 5 * stride];
            float4 v6 = x4[i + 6 * stride];
            float4 v7 = x4[i + 7 * stride];
            mm4(v0, mn0, mx0);
            mm4(v1, mn1, mx1);
            mm4(v2, mn0, mx0);
            mm4(v3, mn1, mx1);
            mm4(v4, mn0, mx0);
            mm4(v5, mn1, mx1);
            mm4(v6, mn0, mx0);
            mm4(v7, mn1, mx1);
        }
        for (; i < n4; i += stride) {
            float4 v = x4[i];
            mm4(v, mn0, mx0);
        }
        if (blockIdx.x == 0) {
            int base = n4 << 2;
            for (int j = base + tid; j < n; j += THREADS_H) {
                float v = x[j];
                mn0 = fminf(mn0, v);
                mx0 = fmaxf(mx0, v);
            }
        }
        float mn = fminf(mn0, mn1);
        float mx = fmaxf(mx0, mx1);

        #pragma unroll
        for (int o = 16; o > 0; o >>= 1) {
            mn = fminf(mn, __shfl_xor_sync(0xFFFFFFFFu, mn, o));
            mx = fmaxf(mx, __shfl_xor_sync(0xFFFFFFFFu, mx, o));
        }
        __shared__ float smn[THREADS_H / 32];
        __shared__ float smx[THREADS_H / 32];
        int wid = tid >> 5;
        int lid = tid & 31;
        if (lid == 0) { smn[wid] = mn; smx[wid] = mx; }
        __syncthreads();
        if (tid == 0) {
            float fmn = smn[0], fmx = smx[0];
            #pragma unroll
            for (int w = 1; w < THREADS_H / 32; w++) {
                fmn = fminf(fmn, smn[w]);
                fmx = fmaxf(fmx, smx[w]);
            }
            g_bmin[blockIdx.x] = fmn;
            g_bmax[blockIdx.x] = fmx;
        }
    }

    // ================= grid barrier (all blocks co-resident) =================
    __threadfence();                 // publish g_bmin/g_bmax
    __syncthreads();                 // all threads' phase-1 work done
    if (tid == 0) {
        atomicAdd((unsigned int*)&g_sync1, 1u);
    }
    for (int j = tid; j < TBL; j += THREADS_H) t2[j] = 0u;   // overlap with spin
    if (tid == 0) {
        while (g_sync1 < GRID_H) { __nanosleep(200); }
    }
    __syncthreads();                 // release whole block
    __threadfence();                 // acquire other blocks' g_bmin/g_bmax

    // ================= global min/max reduce =================
    {
        float mn =  3.402823466e+38f;
        float mx = -3.402823466e+38f;
        for (int j = tid; j < GRID_H; j += THREADS_H) {
            mn = fminf(mn, g_bmin[j]);
            mx = fmaxf(mx, g_bmax[j]);
        }
        #pragma unroll
        for (int o = 16; o > 0; o >>= 1) {
            mn = fminf(mn, __shfl_xor_sync(0xFFFFFFFFu, mn, o));
            mx = fmaxf(mx, __shfl_xor_sync(0xFFFFFFFFu, mx, o));
        }
        __shared__ float rmn[THREADS_H / 32], rmx[THREADS_H / 32];
        int wid = tid >> 5;
        int lid = tid & 31;
        if (lid == 0) { rmn[wid] = mn; rmx[wid] = mx; }
        __syncthreads();
        if (tid == 0) {
            float fmn = rmn[0], fmx = rmx[0];
            #pragma unroll
            for (int w = 1; w < THREADS_H / 32; w++) {
                fmn = fminf(fmn, rmn[w]);
                fmx = fmaxf(fmx, rmx[w]);
            }
            if (fmx == fmn) fmx = fmn + 1.0f;   // degenerate-range guard
            s_hmin = fmn;
            s_hmax = fmx;
        }
        __syncthreads();
    }

    const float hmin  = s_hmin;
    const float scale = (float)NBINS / (s_hmax - hmin);

    // ================= phase 2: pair-binning hist (reverse, 8x unroll) ========
    {
        int i = (n4 - 1) - (int)(blockIdx.x * THREADS_H + tid);

        for (; i - 7 * stride >= 0; i -= 8 * stride) {
            float4 v0 = x4[i];
            float4 v1 = x4[i - stride];
            float4 v2 = x4[i - 2 * stride];
            float4 v3 = x4[i - 3 * stride];
            float4 v4 = x4[i - 4 * stride];
            float4 v5 = x4[i - 5 * stride];
            float4 v6 = x4[i - 6 * stride];
            float4 v7 = x4[i - 7 * stride];
            pair_add(t2, v0, hmin, scale);
            pair_add(t2, v1, hmin, scale);
            pair_add(t2, v2, hmin, scale);
            pair_add(t2, v3, hmin, scale);
            pair_add(t2, v4, hmin, scale);
            pair_add(t2, v5, hmin, scale);
            pair_add(t2, v6, hmin, scale);
            pair_add(t2, v7, hmin, scale);
        }
        for (; i >= 0; i -= stride) {
            float4 v = x4[i];
            pair_add(t2, v, hmin, scale);
        }
        if (blockIdx.x == 0) {
            int base = n4 << 2;
            for (int j = base + tid; j < n; j += THREADS_H) {
                atomicAdd(&g_hist[bin_of(x[j], hmin, scale)], 1u);
            }
        }
        __syncthreads();
    }

    // ---- marginals: one global atomic per (block, bin) for rows and cols ----
    for (int b1 = tid; b1 < NBINS; b1 += THREADS_H) {
        unsigned int s = 0;
        #pragma unroll 8
        for (int b2 = 0; b2 < NBINS; b2++) s += t2[b1 * NBINS + b2];
        if (s) atomicAdd(&g_hist[b1], s);
    }
    for (int b2 = tid; b2 < NBINS; b2 += THREADS_H) {
        unsigned int s = 0;
        #pragma unroll 8
        for (int b1 = 0; b1 < NBINS; b1++) s += t2[b1 * NBINS + b2];
        if (s) atomicAdd(&g_hist[b2], s);
    }

    // ---- finalize: last block converts g_hist -> out, restores global state ----
    __threadfence();
    __syncthreads();
    __shared__ unsigned int s_ticket;
    if (tid == 0) s_ticket = atomicAdd(&g_done, 1u);
    __syncthreads();
    if (s_ticket == GRID_H - 1) {
        __threadfence();
        for (int b = tid; b < NBINS; b += THREADS_H) {
            out[b] = (float)g_hist[b];
            g_hist[b] = 0u;
        }
        if (tid == 0) {
            g_done  = 0u;
            g_sync1 = 0u;   // safe: every block already passed the barrier
        }
    }
}

extern "C" void kernel_launch(void* const* d_in, const int* in_sizes, int n_in,
                              void* d_out, int out_size) {
    const float* x = (const float*)d_in[0];
    int n = in_sizes[0];
    float* out = (float*)d_out;

    fused_kernel<<<GRID_H, THREADS_H>>>(x, n, out);
}

// round 16
// speedup vs baseline: 1.0912x; 1.0912x over previous
#include <cuda_runtime.h>
#include <stdint.h>

#define NBINS     100
#define THREADS_H 1024        // 2 blocks/SM -> 64 warps = full occ
#define GRID_H    296         // 148 SMs * 2 blocks, all co-resident (safe grid sync)
#define TBL       (NBINS * NBINS)   // 10000-entry 2D pair table

__device__ float                 g_bmin[GRID_H];
__device__ float                 g_bmax[GRID_H];
__device__ unsigned int          g_hist[NBINS];  // zero-init; finalize restores zero
__device__ unsigned int          g_done;         // finalize ticket; restored to 0
__device__ volatile unsigned int g_sync1;        // phase-1 barrier; restored to 0

// hmin is the true data min, so (x - hmin) >= 0 exactly; only the upper clamp
// is needed. Keep FADD+FMUL (not fused) to match reference rounding exactly.
__device__ __forceinline__ int bin_of(float x, float hmin, float scale) {
    float d = (x - hmin) * scale;
    int b = __float2int_rd(d);
    return min(b, NBINS - 1);
}

__device__ __forceinline__ void pair_add(unsigned int* t2, const float4& v,
                                         float hmin, float scale) {
    atomicAdd(&t2[bin_of(v.x, hmin, scale) * NBINS + bin_of(v.y, hmin, scale)], 1u);
    atomicAdd(&t2[bin_of(v.z, hmin, scale) * NBINS + bin_of(v.w, hmin, scale)], 1u);
}

// Fused persistent kernel (empirical optimum, R14 configuration):
//   phase 1: forward min/max sweep, 4x float4 unroll (leaves TAIL hot in L2)
//   grid barrier (all 296 blocks co-resident by construction; busy spin)
//   phase 2: reverse pair-binning hist, 8 independent float4 loads in flight
//            (reads hot tail first; leaves HEAD hot for next replay's phase 1)
__global__ void __launch_bounds__(THREADS_H, 2)
fused_kernel(const float* __restrict__ x, int n, float* __restrict__ out) {
    __shared__ unsigned int t2[TBL];        // 40 KB pair table
    __shared__ float s_hmin, s_hmax;

    const int tid = threadIdx.x;
    int n4 = n >> 2;
    const float4* __restrict__ x4 = (const float4*)x;
    const int stride = GRID_H * THREADS_H;

    // ================= phase 1: min/max (forward) =================
    {
        float mn =  3.402823466e+38f;
        float mx = -3.402823466e+38f;

        int i = blockIdx.x * THREADS_H + tid;
        for (; i + 3 * stride < n4; i += 4 * stride) {
            float4 v0 = x4[i];
            float4 v1 = x4[i + stride];
            float4 v2 = x4[i + 2 * stride];
            float4 v3 = x4[i + 3 * stride];
            mn = fminf(mn, fminf(fminf(v0.x, v0.y), fminf(v0.z, v0.w)));
            mx = fmaxf(mx, fmaxf(fmaxf(v0.x, v0.y), fmaxf(v0.z, v0.w)));
            mn = fminf(mn, fminf(fminf(v1.x, v1.y), fminf(v1.z, v1.w)));
            mx = fmaxf(mx, fmaxf(fmaxf(v1.x, v1.y), fmaxf(v1.z, v1.w)));
            mn = fminf(mn, fminf(fminf(v2.x, v2.y), fminf(v2.z, v2.w)));
            mx = fmaxf(mx, fmaxf(fmaxf(v2.x, v2.y), fmaxf(v2.z, v2.w)));
            mn = fminf(mn, fminf(fminf(v3.x, v3.y), fminf(v3.z, v3.w)));
            mx = fmaxf(mx, fmaxf(fmaxf(v3.x, v3.y), fmaxf(v3.z, v3.w)));
        }
        for (; i < n4; i += stride) {
            float4 v = x4[i];
            mn = fminf(mn, fminf(fminf(v.x, v.y), fminf(v.z, v.w)));
            mx = fmaxf(mx, fmaxf(fmaxf(v.x, v.y), fmaxf(v.z, v.w)));
        }
        if (blockIdx.x == 0) {
            int base = n4 << 2;
            for (int j = base + tid; j < n; j += THREADS_H) {
                float v = x[j];
                mn = fminf(mn, v);
                mx = fmaxf(mx, v);
            }
        }

        #pragma unroll
        for (int o = 16; o > 0; o >>= 1) {
            mn = fminf(mn, __shfl_xor_sync(0xFFFFFFFFu, mn, o));
            mx = fmaxf(mx, __shfl_xor_sync(0xFFFFFFFFu, mx, o));
        }
        __shared__ float smn[THREADS_H / 32];
        __shared__ float smx[THREADS_H / 32];
        int wid = tid >> 5;
        int lid = tid & 31;
        if (lid == 0) { smn[wid] = mn; smx[wid] = mx; }
        __syncthreads();
        if (tid == 0) {
            float fmn = smn[0], fmx = smx[0];
            #pragma unroll
            for (int w = 1; w < THREADS_H / 32; w++) {
                fmn = fminf(fmn, smn[w]);
                fmx = fmaxf(fmx, smx[w]);
            }
            g_bmin[blockIdx.x] = fmn;
            g_bmax[blockIdx.x] = fmx;
        }
    }

    // ================= grid barrier (all blocks co-resident) =================
    __threadfence();                 // publish g_bmin/g_bmax
    __syncthreads();                 // all threads' phase-1 work done
    if (tid == 0) {
        atomicAdd((unsigned int*)&g_sync1, 1u);
    }
    for (int j = tid; j < TBL; j += THREADS_H) t2[j] = 0u;   // overlap with spin
    if (tid == 0) {
        while (g_sync1 < GRID_H) { /* spin */ }
    }
    __syncthreads();                 // release whole block
    __threadfence();                 // acquire other blocks' g_bmin/g_bmax

    // ================= global min/max reduce =================
    {
        float mn =  3.402823466e+38f;
        float mx = -3.402823466e+38f;
        for (int j = tid; j < GRID_H; j += THREADS_H) {
            mn = fminf(mn, g_bmin[j]);
            mx = fmaxf(mx, g_bmax[j]);
        }
        #pragma unroll
        for (int o = 16; o > 0; o >>= 1) {
            mn = fminf(mn, __shfl_xor_sync(0xFFFFFFFFu, mn, o));
            mx = fmaxf(mx, __shfl_xor_sync(0xFFFFFFFFu, mx, o));
        }
        __shared__ float rmn[THREADS_H / 32], rmx[THREADS_H / 32];
        int wid = tid >> 5;
        int lid = tid & 31;
        if (lid == 0) { rmn[wid] = mn; rmx[wid] = mx; }
        __syncthreads();
        if (tid == 0) {
            float fmn = rmn[0], fmx = rmx[0];
            #pragma unroll
            for (int w = 1; w < THREADS_H / 32; w++) {
                fmn = fminf(fmn, rmn[w]);
                fmx = fmaxf(fmx, rmx[w]);
            }
            if (fmx == fmn) fmx = fmn + 1.0f;   // degenerate-range guard
            s_hmin = fmn;
            s_hmax = fmx;
        }
        __syncthreads();
    }

    const float hmin  = s_hmin;
    const float scale = (float)NBINS / (s_hmax - hmin);

    // ================= phase 2: pair-binning hist (reverse, 8x unroll) ========
    {
        int i = (n4 - 1) - (int)(blockIdx.x * THREADS_H + tid);

        for (; i - 7 * stride >= 0; i -= 8 * stride) {
            float4 v0 = x4[i];
            float4 v1 = x4[i - stride];
            float4 v2 = x4[i - 2 * stride];
            float4 v3 = x4[i - 3 * stride];
            float4 v4 = x4[i - 4 * stride];
            float4 v5 = x4[i - 5 * stride];
            float4 v6 = x4[i - 6 * stride];
            float4 v7 = x4[i - 7 * stride];
            pair_add(t2, v0, hmin, scale);
            pair_add(t2, v1, hmin, scale);
            pair_add(t2, v2, hmin, scale);
            pair_add(t2, v3, hmin, scale);
            pair_add(t2, v4, hmin, scale);
            pair_add(t2, v5, hmin, scale);
            pair_add(t2, v6, hmin, scale);
            pair_add(t2, v7, hmin, scale);
        }
        for (; i >= 0; i -= stride) {
            float4 v = x4[i];
            pair_add(t2, v, hmin, scale);
        }
        if (blockIdx.x == 0) {
            int base = n4 << 2;
            for (int j = base + tid; j < n; j += THREADS_H) {
                atomicAdd(&g_hist[bin_of(x[j], hmin, scale)], 1u);
            }
        }
        __syncthreads();
    }

    // ---- marginals: one global atomic per (block, bin) for rows and cols ----
    for (int b1 = tid; b1 < NBINS; b1 += THREADS_H) {
        unsigned int s = 0;
        #pragma unroll 4
        for (int b2 = 0; b2 < NBINS; b2++) s += t2[b1 * NBINS + b2];
        if (s) atomicAdd(&g_hist[b1], s);
    }
    for (int b2 = tid; b2 < NBINS; b2 += THREADS_H) {
        unsigned int s = 0;
        #pragma unroll 4
        for (int b1 = 0; b1 < NBINS; b1++) s += t2[b1 * NBINS + b2];
        if (s) atomicAdd(&g_hist[b2], s);
    }

    // ---- finalize: last block converts g_hist -> out, restores global state ----
    __threadfence();
    __syncthreads();
    __shared__ unsigned int s_ticket;
    if (tid == 0) s_ticket = atomicAdd(&g_done, 1u);
    __syncthreads();
    if (s_ticket == GRID_H - 1) {
        __threadfence();
        for (int b = tid; b < NBINS; b += THREADS_H) {
            out[b] = (float)g_hist[b];
            g_hist[b] = 0u;
        }
        if (tid == 0) {
            g_done  = 0u;
            g_sync1 = 0u;   // safe: every block already passed the barrier
        }
    }
}

extern "C" void kernel_launch(void* const* d_in, const int* in_sizes, int n_in,
                              void* d_out, int out_size) {
    const float* x = (const float*)d_in[0];
    int n = in_sizes[0];
    float* out = (float*)d_out;

    fused_kernel<<<GRID_H, THREADS_H>>>(x, n, out);
}